// round 15
// baseline (speedup 1.0000x reference)
#include <cuda_runtime.h>
#include <stdint.h>

#define SEQ 2048
#define DM  1024
#define NH  16
#define DH  64
#define BATCH 4
#define MROWS 8192

// log2(e)/sqrt(64) folded into Q at projection time
#define QSCALE 0.1803368801111204f

// Scratch (device globals: allocation-free), all mma-fragment-packed
__device__ float g_xpack[(size_t)MROWS * DM];            // x as a-frags
__device__ float g_wpack[4 * (size_t)DM * DM];           // W as b-frags
__device__ float g_qpack[(size_t)BATCH * NH * SEQ * DH]; // Q a-frags (scaled)
__device__ float g_kpack[(size_t)BATCH * NH * SEQ * DH]; // K S-gemm b-frags
__device__ float g_vpack[(size_t)BATCH * NH * SEQ * DH]; // V PV-gemm b-frags
__device__ float g_apack[(size_t)MROWS * DM];            // attn out a-frags

// ---------------------------------------------------------------------------
// helpers
// ---------------------------------------------------------------------------
__device__ __forceinline__ float tf32f(float x) {
    unsigned u; asm("cvt.rna.tf32.f32 %0, %1;" : "=r"(u) : "f"(x));
    return __uint_as_float(u);
}
__device__ __forceinline__ unsigned fu(float x) { return __float_as_uint(x); }
__device__ __forceinline__ float ex2f_(float x) {
    float y; asm("ex2.approx.f32 %0, %1;" : "=f"(y) : "f"(x)); return y;
}
__device__ __forceinline__ float rcpf_(float x) {
    float y; asm("rcp.approx.f32 %0, %1;" : "=f"(y) : "f"(x)); return y;
}
__device__ __forceinline__ uint32_t smem_u32(const void* p) {
    uint32_t a;
    asm("{ .reg .u64 t; cvta.to.shared.u64 t, %1; cvt.u32.u64 %0, t; }"
        : "=r"(a) : "l"(p));
    return a;
}
__device__ __forceinline__ void cpa16(uint32_t dst, const void* src) {
    asm volatile("cp.async.cg.shared.global [%0], [%1], 16;"
                 :: "r"(dst), "l"(src));
}
#define CP_COMMIT() asm volatile("cp.async.commit_group;" ::: "memory")
#define CP_WAIT0()  asm volatile("cp.async.wait_group 0;" ::: "memory")
#define CP_WAIT1()  asm volatile("cp.async.wait_group 1;" ::: "memory")

__device__ __forceinline__ void mma8(float* c, const unsigned* a,
                                     unsigned b0, unsigned b1) {
    asm volatile(
        "mma.sync.aligned.m16n8k8.row.col.f32.tf32.tf32.f32 "
        "{%0,%1,%2,%3}, {%4,%5,%6,%7}, {%8,%9}, {%0,%1,%2,%3};"
        : "+f"(c[0]), "+f"(c[1]), "+f"(c[2]), "+f"(c[3])
        : "r"(a[0]), "r"(a[1]), "r"(a[2]), "r"(a[3]), "r"(b0), "r"(b1));
}

// ---------------------------------------------------------------------------
// Pack x into a-frag layout: float4 idx (mtile16*128 + kstep8)*32 + lane
// ---------------------------------------------------------------------------
__global__ __launch_bounds__(256) void xpack_kernel(const float* __restrict__ x)
{
    int t = blockIdx.x * 256 + threadIdx.x;
    int lane = t & 31, ks = (t >> 5) & 127, mt = t >> 12;
    int m = mt * 16 + (lane >> 2), k = ks * 8 + (lane & 3);
    const float* xp = x + (size_t)m * DM + k;
    ((float4*)g_xpack)[t] = make_float4(tf32f(xp[0]), tf32f(xp[8 * DM]),
                                        tf32f(xp[4]), tf32f(xp[8 * DM + 4]));
}

// ---------------------------------------------------------------------------
// Pack W into b-frag layout: float4 idx ((mat*128 + ntile8)*64 + ks4)*32 + lane
// ---------------------------------------------------------------------------
__global__ __launch_bounds__(256) void wpack_kernel(
    const float* __restrict__ Wq, const float* __restrict__ Wk,
    const float* __restrict__ Wv, const float* __restrict__ Wo)
{
    int t = blockIdx.x * 256 + threadIdx.x;
    int lane = t & 31, ks4 = (t >> 5) & 63, nt = (t >> 11) & 127, mat = t >> 18;
    const float* W = (mat == 0) ? Wq : (mat == 1) ? Wk : (mat == 2) ? Wv : Wo;
    int n = nt * 8 + (lane >> 2), k = ks4 * 16 + (lane & 3);
    const float* wp = W + (size_t)k * DM + n;
    ((float4*)g_wpack)[t] = make_float4(tf32f(wp[0]), tf32f(wp[4 * DM]),
                                        tf32f(wp[8 * DM]), tf32f(wp[12 * DM]));
}

// ---------------------------------------------------------------------------
// QKV epilogue scatter into packed layouts (verified in R7/R13)
// ---------------------------------------------------------------------------
__device__ __forceinline__ void qkv_store(int mode, int bh, int s, int d, float v)
{
    if (mode == 0) {
        size_t idx = ((size_t)(bh * 128 + (s >> 4)) * 8 + (d >> 3)) * 128
                   + ((s & 7) * 4 + (d & 3)) * 4 + ((s >> 3) & 1) + 2 * ((d >> 2) & 1);
        g_qpack[idx] = tf32f(v * QSCALE);
    } else if (mode == 1) {
        size_t idx = ((size_t)(bh * 256 + (s >> 3)) * 4 + (d >> 4)) * 128
                   + ((s & 7) * 4 + (d & 3)) * 4 + ((d >> 3) & 1) * 2 + ((d >> 2) & 1);
        g_kpack[idx] = tf32f(v);
    } else {
        size_t idx = ((size_t)(bh * 8 + (d >> 3)) * 128 + (s >> 4)) * 128
                   + ((d & 7) * 4 + (s & 3)) * 4 + ((s >> 3) & 1) * 2 + ((s >> 2) & 1);
        g_vpack[idx] = tf32f(v);
    }
}

// ---------------------------------------------------------------------------
// GEMM: 128x128 block, BK=32, 256 threads, 8 warps (2m x 4n), warp 64x32.
// Packed tiles staged via cp.async; fragments via LDS.128.
// 3-stage ring + wait_group 1: prefetch gets ~2 iterations of slack.
// smem: 3 x (A 16KB + B 16KB) = 96KB; 2 blocks/SM.
// ---------------------------------------------------------------------------
#define GSMEM 98304

__global__ __launch_bounds__(256, 2) void gemm_kernel(
    const float* __restrict__ bq, const float* __restrict__ bk,
    const float* __restrict__ bv, const float* __restrict__ bo,
    float* __restrict__ outp, int pass)
{
    extern __shared__ float fsm[];
    const uint32_t sb = smem_u32(fsm);

    const int mode = (pass == 0) ? (int)blockIdx.z : 3;
    const float* Ap   = (pass == 0) ? g_xpack : g_apack;
    const float* Bp   = g_wpack + (size_t)mode * DM * DM;
    const float* bias = (mode == 0) ? bq : (mode == 1) ? bk
                      : (mode == 2) ? bv : bo;
    const int m0 = blockIdx.y * 128, n0 = blockIdx.x * 128;
    const int tid = threadIdx.x, l = tid & 31, w = tid >> 5;
    const int lq = l >> 2, lr = l & 3;
    const int wm = w & 1, wn = w >> 1;

    float acc[4][4][4] = {};

    const float4* a4 = (const float4*)Ap + (size_t)(m0 >> 4) * 4096;
    const float4* b4 = (const float4*)Bp + (size_t)(n0 >> 3) * 2048;

#define GPF(i)                                                              \
    do {                                                                    \
        uint32_t base_ = sb + (uint32_t)((i) % 3) * 32768;                  \
        _Pragma("unroll")                                                   \
        for (int u = 0; u < 4; ++u) {                                       \
            int f = tid + u * 256;                                          \
            int mt8 = f >> 7, ks = (f >> 5) & 3, ln = f & 31;               \
            cpa16(base_ + f * 16,                                           \
                  a4 + ((size_t)mt8 * 128 + (i) * 4 + ks) * 32 + ln);       \
            int nt8 = f >> 6, ks4 = (f >> 5) & 1;                           \
            cpa16(base_ + 16384 + f * 16,                                   \
                  b4 + ((size_t)nt8 * 64 + (i) * 2 + ks4) * 32 + ln);       \
        }                                                                   \
        CP_COMMIT();                                                        \
    } while (0)

    GPF(0);
    GPF(1);
    for (int i = 0; i < 32; ++i) {
        if (i < 31) CP_WAIT1(); else CP_WAIT0();
        __syncthreads();
        if (i < 30) GPF(i + 2);
        const float4* As4 = (const float4*)(fsm + (i % 3) * 8192);
        const float4* Bs4 = As4 + 1024;
#pragma unroll
        for (int ks4 = 0; ks4 < 2; ++ks4) {
            float4 bf[4];
#pragma unroll
            for (int nt = 0; nt < 4; ++nt)
                bf[nt] = Bs4[((wn * 4 + nt) * 2 + ks4) * 32 + l];
#pragma unroll
            for (int h = 0; h < 2; ++h) {
                float4 af[4];
#pragma unroll
                for (int mt = 0; mt < 4; ++mt)
                    af[mt] = As4[((wm * 4 + mt) * 4 + ks4 * 2 + h) * 32 + l];
#pragma unroll
                for (int mt = 0; mt < 4; ++mt)
#pragma unroll
                    for (int nt = 0; nt < 4; ++nt)
                        mma8(acc[mt][nt], (const unsigned*)&af[mt],
                             h ? fu(bf[nt].z) : fu(bf[nt].x),
                             h ? fu(bf[nt].w) : fu(bf[nt].y));
            }
        }
    }
#undef GPF

    if (mode == 3) {
#pragma unroll
        for (int mt = 0; mt < 4; ++mt) {
            int mrow = m0 + wm * 64 + mt * 16 + lq;
#pragma unroll
            for (int nt = 0; nt < 4; ++nt) {
                int col = n0 + wn * 32 + nt * 8 + 2 * lr;
                float2 bx = *(const float2*)(bias + col);
                *(float2*)(outp + (size_t)mrow * DM + col) =
                    make_float2(acc[mt][nt][0] + bx.x, acc[mt][nt][1] + bx.y);
                *(float2*)(outp + (size_t)(mrow + 8) * DM + col) =
                    make_float2(acc[mt][nt][2] + bx.x, acc[mt][nt][3] + bx.y);
            }
        }
    } else {
#pragma unroll
        for (int mt = 0; mt < 4; ++mt) {
            int mrow = m0 + wm * 64 + mt * 16 + lq;
            int bb = mrow >> 11, s = mrow & 2047;
#pragma unroll
            for (int nt = 0; nt < 4; ++nt) {
                int col = n0 + wn * 32 + nt * 8 + 2 * lr;
                int bh = bb * 16 + (col >> 6), d = col & 63;
                float b0 = bias[col], b1 = bias[col + 1];
                qkv_store(mode, bh, s,     d,     acc[mt][nt][0] + b0);
                qkv_store(mode, bh, s,     d + 1, acc[mt][nt][1] + b1);
                qkv_store(mode, bh, s + 8, d,     acc[mt][nt][2] + b0);
                qkv_store(mode, bh, s + 8, d + 1, acc[mt][nt][3] + b1);
            }
        }
    }
}

// ---------------------------------------------------------------------------
// Causal flash attention (unchanged from R14 passing version).
// ---------------------------------------------------------------------------
#define ATTN_SMEM ((8704 + 8192 + 8192) * 4)   // 100352 B

__global__ __launch_bounds__(256, 2) void attn_kernel()
{
    extern __shared__ float sm[];
    const uint32_t sb = smem_u32(sm);
    float* Pq = sm;                        // P region [128][68]

    const int qb  = 15 - blockIdx.x;       // heavy tiles first
    const int bh  = blockIdx.y;
    const int tid = threadIdx.x, w = tid >> 5, l = tid & 31;
    const int lq = l >> 2, lr = l & 3;
    const int r0 = w * 16 + lq;

    const float4* qg = (const float4*)g_qpack + (size_t)(bh * 128 + qb * 8) * 256;
    const float4* kg = (const float4*)g_kpack + (size_t)bh * 32768;
    const float4* vg = (const float4*)g_vpack + (size_t)bh * 32768;

#define KVPF(t)                                                             \
    do {                                                                    \
        uint32_t kb_ = sb + 34816 + ((t) & 1) * 16384;                      \
        uint32_t vb_ = sb + 67584 + ((t) & 1) * 16384;                      \
        _Pragma("unroll")                                                   \
        for (int u = 0; u < 4; ++u) {                                       \
            int f = tid + u * 256;                                          \
            cpa16(kb_ + f * 16, kg + (size_t)(t) * 1024 + f);               \
            cpa16(vb_ + f * 16,                                             \
                  vg + ((size_t)(f >> 7) * 4096 + (t) * 128 + (f & 127)));  \
        }                                                                   \
        CP_COMMIT();                                                        \
    } while (0)

    KVPF(0);

    // Q fragments straight from packed global (identical bits to staged path)
    float4 qa4[8];
#pragma unroll
    for (int s = 0; s < 8; ++s) qa4[s] = qg[(w * 8 + s) * 32 + l];

    CP_WAIT0();
    __syncthreads();

    float m0v = -1e30f, m1v = -1e30f, l0v = 0.0f, l1v = 0.0f;
    float o[8][4] = {};

    const int ktmax = 2 * qb + 1;
    for (int kt = 0; kt <= ktmax; ++kt) {
        if (kt > 0) { CP_WAIT0(); __syncthreads(); }
        if (kt < ktmax) KVPF(kt + 1);

        const float4* Ks4 = (const float4*)(sm + 8704 + (kt & 1) * 4096);
        const float4* Vs4 = (const float4*)(sm + 16896 + (kt & 1) * 4096);

        // ---- S = Q K^T : 32 LDS.128 + 64 mma ----
        float sc[8][4] = {};
#pragma unroll
        for (int sp = 0; sp < 4; ++sp)
#pragma unroll
            for (int nt = 0; nt < 8; ++nt) {
                float4 b4 = Ks4[(nt * 4 + sp) * 32 + l];
                mma8(sc[nt], (const unsigned*)&qa4[2 * sp],     fu(b4.x), fu(b4.y));
                mma8(sc[nt], (const unsigned*)&qa4[2 * sp + 1], fu(b4.z), fu(b4.w));
            }

        // ---- causal mask (last two tiles only) ----
        if (kt >= 2 * qb) {
            int qg0 = qb * 128 + r0, qg1 = qg0 + 8;
#pragma unroll
            for (int nt = 0; nt < 8; ++nt) {
                int kg2 = kt * 64 + nt * 8 + 2 * lr;
                if (kg2 > qg0)     sc[nt][0] = -1e30f;
                if (kg2 + 1 > qg0) sc[nt][1] = -1e30f;
                if (kg2 > qg1)     sc[nt][2] = -1e30f;
                if (kg2 + 1 > qg1) sc[nt][3] = -1e30f;
            }
        }

        // ---- online softmax (log2 domain), 2 rows per lane ----
        float mx0 = -1e30f, mx1 = -1e30f;
#pragma unroll
        for (int nt = 0; nt < 8; ++nt) {
            mx0 = fmaxf(mx0, fmaxf(sc[nt][0], sc[nt][1]));
            mx1 = fmaxf(mx1, fmaxf(sc[nt][2], sc[nt][3]));
        }
        mx0 = fmaxf(mx0, __shfl_xor_sync(0xffffffffu, mx0, 1));
        mx0 = fmaxf(mx0, __shfl_xor_sync(0xffffffffu, mx0, 2));
        mx1 = fmaxf(mx1, __shfl_xor_sync(0xffffffffu, mx1, 1));
        mx1 = fmaxf(mx1, __shfl_xor_sync(0xffffffffu, mx1, 2));

        float mn0 = fmaxf(m0v, mx0), mn1 = fmaxf(m1v, mx1);
        float al0 = ex2f_(m0v - mn0), al1 = ex2f_(m1v - mn1);
        m0v = mn0; m1v = mn1;

        float rs0 = 0.0f, rs1 = 0.0f;
#pragma unroll
        for (int nt = 0; nt < 8; ++nt) {
            sc[nt][0] = ex2f_(sc[nt][0] - mn0);
            sc[nt][1] = ex2f_(sc[nt][1] - mn0);
            sc[nt][2] = ex2f_(sc[nt][2] - mn1);
            sc[nt][3] = ex2f_(sc[nt][3] - mn1);
            rs0 += sc[nt][0] + sc[nt][1];
            rs1 += sc[nt][2] + sc[nt][3];
        }
        rs0 += __shfl_xor_sync(0xffffffffu, rs0, 1);
        rs0 += __shfl_xor_sync(0xffffffffu, rs0, 2);
        rs1 += __shfl_xor_sync(0xffffffffu, rs1, 1);
        rs1 += __shfl_xor_sync(0xffffffffu, rs1, 2);
        l0v = l0v * al0 + rs0;
        l1v = l1v * al1 + rs1;
#pragma unroll
        for (int nt = 0; nt < 8; ++nt) {
            o[nt][0] *= al0; o[nt][1] *= al0;
            o[nt][2] *= al1; o[nt][3] *= al1;
        }

        // ---- P round-trip (warp-private rows: no block barrier) ----
        __syncwarp();
#pragma unroll
        for (int nt = 0; nt < 8; ++nt) {
            *(float2*)&Pq[r0 * 68 + 8 * nt + 2 * lr] =
                make_float2(sc[nt][0], sc[nt][1]);
            *(float2*)&Pq[(r0 + 8) * 68 + 8 * nt + 2 * lr] =
                make_float2(sc[nt][2], sc[nt][3]);
        }
        __syncwarp();

        // ---- O += P V : 32 LDS.128 (V) + 64 mma ----
#pragma unroll
        for (int sp = 0; sp < 4; ++sp) {
            unsigned pe[4], po[4];
            pe[0] = fu(Pq[r0 * 68 + 16 * sp + lr]);
            pe[1] = fu(Pq[(r0 + 8) * 68 + 16 * sp + lr]);
            pe[2] = fu(Pq[r0 * 68 + 16 * sp + 4 + lr]);
            pe[3] = fu(Pq[(r0 + 8) * 68 + 16 * sp + 4 + lr]);
            po[0] = fu(Pq[r0 * 68 + 16 * sp + 8 + lr]);
            po[1] = fu(Pq[(r0 + 8) * 68 + 16 * sp + 8 + lr]);
            po[2] = fu(Pq[r0 * 68 + 16 * sp + 12 + lr]);
            po[3] = fu(Pq[(r0 + 8) * 68 + 16 * sp + 12 + lr]);
#pragma unroll
            for (int nt = 0; nt < 8; ++nt) {
                float4 v4 = Vs4[(nt * 4 + sp) * 32 + l];
                mma8(o[nt], pe, fu(v4.x), fu(v4.y));
                mma8(o[nt], po, fu(v4.z), fu(v4.w));
            }
        }
    }
#undef KVPF

    // ---- epilogue: normalize, store a-frag-packed for oproj ----
    float i0 = rcpf_(l0v), i1 = rcpf_(l1v);
    const int b = bh >> 4, h = bh & 15;
    const size_t mtbase = (size_t)(b * 128 + qb * 8 + w) * 128;
#pragma unroll
    for (int nt = 0; nt < 8; ++nt) {
#pragma unroll
        for (int i = 0; i < 2; ++i) {
            int n = h * 64 + nt * 8 + 2 * lr + i;
            size_t base = (mtbase + (n >> 3)) * 128
                        + (lq * 4 + (n & 3)) * 4 + 2 * ((n >> 2) & 1);
            g_apack[base]     = tf32f(o[nt][i]     * i0);
            g_apack[base + 1] = tf32f(o[nt][2 + i] * i1);
        }
    }
}

// ---------------------------------------------------------------------------
extern "C" void kernel_launch(void* const* d_in, const int* in_sizes, int n_in,
                              void* d_out, int out_size)
{
    const float* x  = (const float*)d_in[0];
    const float* Wq = (const float*)d_in[1];
    const float* bq = (const float*)d_in[2];
    const float* Wk = (const float*)d_in[3];
    const float* bk = (const float*)d_in[4];
    const float* Wv = (const float*)d_in[5];
    const float* bv = (const float*)d_in[6];
    const float* Wo = (const float*)d_in[7];
    const float* bo = (const float*)d_in[8];

    cudaFuncSetAttribute(gemm_kernel,
                         cudaFuncAttributeMaxDynamicSharedMemorySize, GSMEM);
    cudaFuncSetAttribute(gemm_kernel,
                         cudaFuncAttributePreferredSharedMemoryCarveout, 100);
    cudaFuncSetAttribute(attn_kernel,
                         cudaFuncAttributeMaxDynamicSharedMemorySize, ATTN_SMEM);
    cudaFuncSetAttribute(attn_kernel,
                         cudaFuncAttributePreferredSharedMemoryCarveout, 100);

    xpack_kernel<<<8192, 256>>>(x);
    wpack_kernel<<<4096, 256>>>(Wq, Wk, Wv, Wo);
    gemm_kernel<<<dim3(8, 64, 3), 256, GSMEM>>>(bq, bk, bv, bo, nullptr, 0);
    attn_kernel<<<dim3(16, 64), 256, ATTN_SMEM>>>();
    gemm_kernel<<<dim3(8, 64, 1), 256, GSMEM>>>(bq, bk, bv, bo,
                                                (float*)d_out, 1);
}